// round 16
// baseline (speedup 1.0000x reference)
#include <cuda_runtime.h>
#include <cuda_bf16.h>
#include <cstdint>

// Householder: out = z - 2*v_new*(v_new.z)/||v_new||^2, v_new = v@W.T + b
// mma.sync bf16 hi/lo (3-product) warp GEMM computing v_new^T = W @ v^T.
// W fragments register-resident; persistent CTAs; fused epilogue.
// R16: MMA loop interchanged (s outer, nb2 inner) -> 16 independent
// accumulator chains instead of one 24-deep serial chain per d-reg.

#define NTHREADS 256
#define ROWB 272            // bytes per bf16 tile row (128*2 + 16 pad) -> conflict-free ldmatrix
#define LO_OFF 34816        // 128*272: lo tile offset within a buffer
#define VT_STRIDE 132       // f32 words per v_new row (conflict-free scatter)

#define SM_C    0           // 128 f32 cvals
#define SM_BUF0 1024
#define SM_BUFSZ 69632      // hi+lo bf16 tiles (vt overlay: 128*132*4=67584 fits)
#define SM_BUF1 (SM_BUF0 + SM_BUFSZ)
#define SM_TOTAL (SM_BUF1 + SM_BUFSZ)   // 140288

__device__ __forceinline__ uint32_t smem_u32(const void* p) {
    uint32_t a;
    asm("{ .reg .u64 t; cvta.to.shared.u64 t, %1; cvt.u32.u64 %0, t; }" : "=r"(a) : "l"(p));
    return a;
}

#define LDSM_X4(r0, r1, r2, r3, addr) \
    asm volatile("ldmatrix.sync.aligned.m8n8.x4.shared.b16 {%0,%1,%2,%3}, [%4];" \
                 : "=r"(r0), "=r"(r1), "=r"(r2), "=r"(r3) : "r"(addr))

__device__ __forceinline__ void mma_bf16(float* d, const uint32_t* a,
                                         uint32_t b0, uint32_t b1) {
    asm volatile(
        "mma.sync.aligned.m16n8k16.row.col.f32.bf16.bf16.f32 "
        "{%0,%1,%2,%3}, {%4,%5,%6,%7}, {%8,%9}, {%0,%1,%2,%3};"
        : "+f"(d[0]), "+f"(d[1]), "+f"(d[2]), "+f"(d[3])
        : "r"(a[0]), "r"(a[1]), "r"(a[2]), "r"(a[3]), "r"(b0), "r"(b1));
}

// split one float4 into bf16 hi/lo pairs and store (8B each) to padded-row tile
__device__ __forceinline__ void split_store(char* sm, uint32_t dst, int row, int col,
                                            float4 x) {
    __nv_bfloat16 h0 = __float2bfloat16(x.x);
    __nv_bfloat16 h1 = __float2bfloat16(x.y);
    __nv_bfloat16 h2 = __float2bfloat16(x.z);
    __nv_bfloat16 h3 = __float2bfloat16(x.w);
    __nv_bfloat16 l0 = __float2bfloat16(x.x - __bfloat162float(h0));
    __nv_bfloat16 l1 = __float2bfloat16(x.y - __bfloat162float(h1));
    __nv_bfloat16 l2 = __float2bfloat16(x.z - __bfloat162float(h2));
    __nv_bfloat16 l3 = __float2bfloat16(x.w - __bfloat162float(h3));
    union { __nv_bfloat162 b[2]; uint2 u; } hp, lp;
    hp.b[0] = __halves2bfloat162(h0, h1);
    hp.b[1] = __halves2bfloat162(h2, h3);
    lp.b[0] = __halves2bfloat162(l0, l1);
    lp.b[1] = __halves2bfloat162(l2, l3);
    const uint32_t off = (uint32_t)(row * ROWB + col * 2);
    *(uint2*)(sm + dst + off)          = hp.u;
    *(uint2*)(sm + dst + LO_OFF + off) = lp.u;
}

// full 128x128 fp32 tile -> hi/lo bf16 padded tiles
__device__ __forceinline__ void load_convert(const float* __restrict__ src, char* sm,
                                             uint32_t dst, int tid) {
    #pragma unroll
    for (int i = 0; i < 16; i++) {
        const int e = (tid + i * NTHREADS) * 4;
        split_store(sm, dst, e >> 7, e & 127, *(const float4*)(src + e));
    }
}

extern "C" __global__ void __launch_bounds__(NTHREADS, 1)
hh_kernel(const float* __restrict__ z, const float* __restrict__ v,
          const float* __restrict__ W, const float* __restrict__ b,
          float* __restrict__ out, int ntiles)
{
    extern __shared__ char sm[];
    const uint32_t sb = smem_u32(sm);
    const int tid  = threadIdx.x;
    const int wid  = tid >> 5;
    const int lane = tid & 31;

    // ---- stage W (hi/lo) in BUF0, ldmatrix A-fragments into registers ----
    load_convert(W, sm, SM_BUF0, tid);
    __syncthreads();

    uint32_t Ahi[8][4], Alo[8][4];
    {
        // lane -> matrix i = lane/8: row = wid*16 + (i&1)*8 + lane%8, kbyte = (i>>1)*16
        const int i = lane >> 3;
        const uint32_t rowa = (uint32_t)(wid * 16 + ((i & 1) << 3) + (lane & 7));
        const uint32_t abase = sb + SM_BUF0 + rowa * ROWB + (uint32_t)((i >> 1) * 16);
        #pragma unroll
        for (int s = 0; s < 8; s++) {
            LDSM_X4(Ahi[s][0], Ahi[s][1], Ahi[s][2], Ahi[s][3], abase + s * 32);
            LDSM_X4(Alo[s][0], Alo[s][1], Alo[s][2], Alo[s][3], abase + LO_OFF + s * 32);
        }
    }
    const float bs0 = b[wid * 16 + (lane >> 2)];
    const float bs8 = b[wid * 16 + (lane >> 2) + 8];
    __syncthreads();

    // ---- first v tile into BUF0 ----
    const int grid = gridDim.x;
    int tile = blockIdx.x;
    if (tile < ntiles)
        load_convert(v + ((size_t)tile << 14), sm, SM_BUF0, tid);
    __syncthreads();

    // B-frag lane offset: matrix i = lane/8: row = (i>>1)*8 + lane%8, kbyte = (i&1)*16
    const uint32_t bloff = (uint32_t)((((lane >> 4) << 3) + (lane & 7)) * ROWB
                                      + (((lane >> 3) & 1) << 4));
    float* cvals = (float*)(sm + SM_C);

    int m = 0;
    for (; tile < ntiles; tile += grid, m++) {
        const uint32_t cur = (m & 1) ? SM_BUF1 : SM_BUF0;
        const uint32_t nxt = (m & 1) ? SM_BUF0 : SM_BUF1;
        const bool has = (tile + grid) < ntiles;
        const float* nsrc = v + ((size_t)(tile + grid) << 14);

        float D[64];
        #pragma unroll
        for (int i = 0; i < 64; i++) D[i] = 0.f;

        // prefetch wave 0 (8 float4)
        float4 pf[8];
        if (has) {
            #pragma unroll
            for (int i = 0; i < 8; i++)
                pf[i] = *(const float4*)(nsrc + (size_t)(tid + i * NTHREADS) * 4);
        }

        // ---- MMA mainloop: s OUTER, nb2 INNER -> adjacent MMAs hit
        //      independent accumulators; each d-reg revisited only once
        //      per s (distance ~45 instructions, hides HMMA latency) ----
        const uint32_t bh_base = sb + cur + bloff;
        #pragma unroll
        for (int s = 0; s < 8; s++) {
            #pragma unroll
            for (int nb2 = 0; nb2 < 8; nb2++) {
                uint32_t h0, h1, h2, h3, l0, l1, l2, l3;
                const uint32_t a = bh_base + (uint32_t)(nb2 * 4352 + s * 32);
                LDSM_X4(h0, h1, h2, h3, a);
                LDSM_X4(l0, l1, l2, l3, a + LO_OFF);
                float* d0 = D + nb2 * 8;
                float* d1 = d0 + 4;
                mma_bf16(d0, Ahi[s], h0, h1);
                mma_bf16(d1, Ahi[s], h2, h3);
                mma_bf16(d0, Ahi[s], l0, l1);
                mma_bf16(d1, Ahi[s], l2, l3);
                mma_bf16(d0, Alo[s], h0, h1);
                mma_bf16(d1, Alo[s], h2, h3);
            }
            if (s == 1 && has) {        // drain wave 0
                #pragma unroll
                for (int i = 0; i < 8; i++) {
                    const int e = (tid + i * NTHREADS) * 4;
                    split_store(sm, nxt, e >> 7, e & 127, pf[i]);
                }
            }
            if (s == 2 && has) {        // issue wave 1
                #pragma unroll
                for (int i = 0; i < 8; i++)
                    pf[i] = *(const float4*)(nsrc + (size_t)(tid + (i + 8) * NTHREADS) * 4);
            }
            if (s == 5 && has) {        // drain wave 1
                #pragma unroll
                for (int i = 0; i < 8; i++) {
                    const int e = (tid + (i + 8) * NTHREADS) * 4;
                    split_store(sm, nxt, e >> 7, e & 127, pf[i]);
                }
            }
        }
        __syncthreads();   // all warps done reading cur

        // ---- store v_new (D + bias) row-major into cur, stride 132 ----
        float* vt = (float*)(sm + cur);
        const int ccol = wid * 16 + (lane >> 2);
        const int rr   = (lane & 3) * 2;
        #pragma unroll
        for (int nb = 0; nb < 16; nb++) {
            const int rb = nb * 8 + rr;
            vt[(rb + 0) * VT_STRIDE + ccol]     = D[nb * 4 + 0] + bs0;
            vt[(rb + 1) * VT_STRIDE + ccol]     = D[nb * 4 + 1] + bs0;
            vt[(rb + 0) * VT_STRIDE + ccol + 8] = D[nb * 4 + 2] + bs8;
            vt[(rb + 1) * VT_STRIDE + ccol + 8] = D[nb * 4 + 3] + bs8;
        }
        __syncthreads();

        // ---- per-row c = 2*(v_new.z)/||v_new||^2 ----
        const float* zt = z + ((size_t)tile << 14);
        #pragma unroll 4
        for (int j = 0; j < 16; j++) {
            const int r = wid * 16 + j;
            float dot = 0.f, ns = 0.f;
            #pragma unroll
            for (int q = 0; q < 4; q++) {
                const int c = lane + q * 32;
                const float vn = vt[r * VT_STRIDE + c];
                const float zz = __ldg(zt + r * 128 + c);
                dot = fmaf(vn, zz, dot);
                ns  = fmaf(vn, vn, ns);
            }
            #pragma unroll
            for (int o = 16; o > 0; o >>= 1) {
                dot += __shfl_xor_sync(0xFFFFFFFFu, dot, o);
                ns  += __shfl_xor_sync(0xFFFFFFFFu, ns,  o);
            }
            if (lane == 0) cvals[r] = 2.0f * dot / ns;
        }
        __syncthreads();

        // ---- out = z - c[r]*v_new ----
        float* ot = out + ((size_t)tile << 14);
        #pragma unroll 8
        for (int i = 0; i < 64; i++) {
            const int e = tid + i * NTHREADS;
            const int r = e >> 7;
            const int c = e & 127;
            ot[e] = fmaf(-cvals[r], vt[r * VT_STRIDE + c], __ldg(zt + e));
        }
        __syncthreads();
    }
}

extern "C" void kernel_launch(void* const* d_in, const int* in_sizes, int n_in,
                              void* d_out, int out_size) {
    const float* z = (const float*)d_in[0];
    const float* v = (const float*)d_in[1];
    const float* W = (const float*)d_in[2];
    const float* b = (const float*)d_in[3];
    float* out = (float*)d_out;

    const int ntiles = in_sizes[0] >> 14;   // rows/128

    cudaFuncSetAttribute(hh_kernel, cudaFuncAttributeMaxDynamicSharedMemorySize, SM_TOTAL);

    int sms = 148;
    cudaDeviceGetAttribute(&sms, cudaDevAttrMultiProcessorCount, 0);
    int grid = sms;
    if (grid > ntiles) grid = ntiles;
    if (grid < 1) grid = 1;

    hh_kernel<<<grid, NTHREADS, SM_TOTAL>>>(z, v, W, b, out, ntiles);
}

// round 17
// speedup vs baseline: 1.3834x; 1.3834x over previous
#include <cuda_runtime.h>
#include <cuda_bf16.h>
#include <cstdint>

// Householder: out = z - 2*v_new*(v_new.z)/||v_new||^2, v_new = v@W.T + b
// R17: 512 threads / 16 warps (4 per SMSP) to fix latency-bound occ=12.5%.
// Warp (wm=w&7, wg=w>>3): output dims 16*wm.., batch rows 64*wg..
// A-hi register-resident (32 regs); A-lo streamed from persistent SMEM W-lo.

#define NTHREADS 512
#define ROWB 272            // bytes per bf16 tile row (128*2 + 16 pad)
#define LO_OFF 34816        // 128*272: lo tile offset within a v buffer
#define VT_STRIDE 132       // f32 words per v_new row (conflict-free scatter)
#define WLO_BYTES 34816

#define SM_C    0           // 128 f32 cvals
#define SM_WLO  1024        // persistent W-lo bf16 tile (34816B)
#define SM_BUF0 (SM_WLO + WLO_BYTES)          // 35840
#define SM_BUFSZ 69632      // hi+lo bf16 v tiles (vt overlay 67584 fits)
#define SM_BUF1 (SM_BUF0 + SM_BUFSZ)          // 105472
#define SM_TOTAL (SM_BUF1 + SM_BUFSZ)         // 175104

__device__ __forceinline__ uint32_t smem_u32(const void* p) {
    uint32_t a;
    asm("{ .reg .u64 t; cvta.to.shared.u64 t, %1; cvt.u32.u64 %0, t; }" : "=r"(a) : "l"(p));
    return a;
}

#define LDSM_X4(r0, r1, r2, r3, addr) \
    asm volatile("ldmatrix.sync.aligned.m8n8.x4.shared.b16 {%0,%1,%2,%3}, [%4];" \
                 : "=r"(r0), "=r"(r1), "=r"(r2), "=r"(r3) : "r"(addr))

__device__ __forceinline__ void mma_bf16(float* d, const uint32_t* a,
                                         uint32_t b0, uint32_t b1) {
    asm volatile(
        "mma.sync.aligned.m16n8k16.row.col.f32.bf16.bf16.f32 "
        "{%0,%1,%2,%3}, {%4,%5,%6,%7}, {%8,%9}, {%0,%1,%2,%3};"
        : "+f"(d[0]), "+f"(d[1]), "+f"(d[2]), "+f"(d[3])
        : "r"(a[0]), "r"(a[1]), "r"(a[2]), "r"(a[3]), "r"(b0), "r"(b1));
}

__device__ __forceinline__ void split4(float4 x, uint2& hu, uint2& lu) {
    __nv_bfloat16 h0 = __float2bfloat16(x.x);
    __nv_bfloat16 h1 = __float2bfloat16(x.y);
    __nv_bfloat16 h2 = __float2bfloat16(x.z);
    __nv_bfloat16 h3 = __float2bfloat16(x.w);
    __nv_bfloat16 l0 = __float2bfloat16(x.x - __bfloat162float(h0));
    __nv_bfloat16 l1 = __float2bfloat16(x.y - __bfloat162float(h1));
    __nv_bfloat16 l2 = __float2bfloat16(x.z - __bfloat162float(h2));
    __nv_bfloat16 l3 = __float2bfloat16(x.w - __bfloat162float(h3));
    union { __nv_bfloat162 b[2]; uint2 u; } hp, lp;
    hp.b[0] = __halves2bfloat162(h0, h1);
    hp.b[1] = __halves2bfloat162(h2, h3);
    lp.b[0] = __halves2bfloat162(l0, l1);
    lp.b[1] = __halves2bfloat162(l2, l3);
    hu = hp.u; lu = lp.u;
}

// v tile: hi at dst+off, lo at dst+LO_OFF+off
__device__ __forceinline__ void split_store_v(char* sm, uint32_t dst, int e, float4 x) {
    uint2 hu, lu;
    split4(x, hu, lu);
    const uint32_t off = (uint32_t)((e >> 7) * ROWB + (e & 127) * 2);
    *(uint2*)(sm + dst + off)          = hu;
    *(uint2*)(sm + dst + LO_OFF + off) = lu;
}

// full 128x128 fp32 v tile -> hi/lo bf16 tiles (512 threads: 8 float4 each)
__device__ __forceinline__ void load_convert_v(const float* __restrict__ src, char* sm,
                                               uint32_t dst, int tid) {
    #pragma unroll
    for (int i = 0; i < 8; i++) {
        const int e = (tid + i * NTHREADS) * 4;
        split_store_v(sm, dst, e, *(const float4*)(src + e));
    }
}

extern "C" __global__ void __launch_bounds__(NTHREADS, 1)
hh_kernel(const float* __restrict__ z, const float* __restrict__ v,
          const float* __restrict__ W, const float* __restrict__ b,
          float* __restrict__ out, int ntiles)
{
    extern __shared__ char sm[];
    const uint32_t sb = smem_u32(sm);
    const int tid  = threadIdx.x;
    const int wid  = tid >> 5;
    const int lane = tid & 31;
    const int wm   = wid & 7;    // output-dim group (16 dims)
    const int wg   = wid >> 3;   // batch half (64 rows)

    // ---- stage W: hi -> BUF0 (temp), lo -> SM_WLO (persistent) ----
    #pragma unroll
    for (int i = 0; i < 8; i++) {
        const int e = (tid + i * NTHREADS) * 4;
        uint2 hu, lu;
        split4(*(const float4*)(W + e), hu, lu);
        const uint32_t off = (uint32_t)((e >> 7) * ROWB + (e & 127) * 2);
        *(uint2*)(sm + SM_BUF0 + off) = hu;
        *(uint2*)(sm + SM_WLO + off)  = lu;
    }
    __syncthreads();

    // A-hi fragments into registers; A-lo address base (streamed per s)
    uint32_t Ahi[8][4];
    uint32_t alo_base;
    {
        const int i = lane >> 3;
        const uint32_t rowa = (uint32_t)(wm * 16 + ((i & 1) << 3) + (lane & 7));
        const uint32_t roff = rowa * ROWB + (uint32_t)((i >> 1) * 16);
        const uint32_t abase = sb + SM_BUF0 + roff;
        alo_base = sb + SM_WLO + roff;
        #pragma unroll
        for (int s = 0; s < 8; s++)
            LDSM_X4(Ahi[s][0], Ahi[s][1], Ahi[s][2], Ahi[s][3], abase + s * 32);
    }
    const float bs0 = b[wm * 16 + (lane >> 2)];
    const float bs8 = b[wm * 16 + (lane >> 2) + 8];
    __syncthreads();

    // ---- first v tile into BUF0 ----
    const int grid = gridDim.x;
    int tile = blockIdx.x;
    if (tile < ntiles)
        load_convert_v(v + ((size_t)tile << 14), sm, SM_BUF0, tid);
    __syncthreads();

    // B-frag lane offset within this warp's 64-row half
    const uint32_t bloff = (uint32_t)(wg * 64 * ROWB)
                         + (uint32_t)((((lane >> 4) << 3) + (lane & 7)) * ROWB
                                      + (((lane >> 3) & 1) << 4));
    float* cvals = (float*)(sm + SM_C);

    int m = 0;
    for (; tile < ntiles; tile += grid, m++) {
        const uint32_t cur = (m & 1) ? SM_BUF1 : SM_BUF0;
        const uint32_t nxt = (m & 1) ? SM_BUF0 : SM_BUF1;
        const bool has = (tile + grid) < ntiles;
        const float* nsrc = v + ((size_t)(tile + grid) << 14);

        float D[32];
        #pragma unroll
        for (int i = 0; i < 32; i++) D[i] = 0.f;

        // prefetch wave 0 (4 float4)
        float4 pf[4];
        if (has) {
            #pragma unroll
            for (int i = 0; i < 4; i++)
                pf[i] = *(const float4*)(nsrc + (size_t)(tid + i * NTHREADS) * 4);
        }

        const uint32_t bh_base = sb + cur + bloff;
        #pragma unroll
        for (int s = 0; s < 8; s++) {
            uint32_t Alo[4];
            LDSM_X4(Alo[0], Alo[1], Alo[2], Alo[3], alo_base + s * 32);
            #pragma unroll
            for (int nb2 = 0; nb2 < 4; nb2++) {
                uint32_t h0, h1, h2, h3, l0, l1, l2, l3;
                const uint32_t a = bh_base + (uint32_t)(nb2 * 4352 + s * 32);
                LDSM_X4(h0, h1, h2, h3, a);
                LDSM_X4(l0, l1, l2, l3, a + LO_OFF);
                float* d0 = D + nb2 * 8;
                float* d1 = d0 + 4;
                mma_bf16(d0, Ahi[s], h0, h1);
                mma_bf16(d1, Ahi[s], h2, h3);
                mma_bf16(d0, Ahi[s], l0, l1);
                mma_bf16(d1, Ahi[s], l2, l3);
                mma_bf16(d0, Alo, h0, h1);
                mma_bf16(d1, Alo, h2, h3);
            }
            if (s == 1 && has) {        // drain wave 0
                #pragma unroll
                for (int i = 0; i < 4; i++)
                    split_store_v(sm, nxt, (tid + i * NTHREADS) * 4, pf[i]);
            }
            if (s == 2 && has) {        // issue wave 1
                #pragma unroll
                for (int i = 0; i < 4; i++)
                    pf[i] = *(const float4*)(nsrc + (size_t)(tid + (i + 4) * NTHREADS) * 4);
            }
            if (s == 5 && has) {        // drain wave 1
                #pragma unroll
                for (int i = 0; i < 4; i++)
                    split_store_v(sm, nxt, (tid + (i + 4) * NTHREADS) * 4, pf[i]);
            }
        }
        __syncthreads();   // all warps done reading cur

        // ---- store v_new (D + bias) row-major into cur, stride 132 ----
        float* vt = (float*)(sm + cur);
        const int ccol = wm * 16 + (lane >> 2);
        const int rr   = wg * 64 + (lane & 3) * 2;
        #pragma unroll
        for (int nb = 0; nb < 8; nb++) {
            const int rb = nb * 8 + rr;
            vt[(rb + 0) * VT_STRIDE + ccol]     = D[nb * 4 + 0] + bs0;
            vt[(rb + 1) * VT_STRIDE + ccol]     = D[nb * 4 + 1] + bs0;
            vt[(rb + 0) * VT_STRIDE + ccol + 8] = D[nb * 4 + 2] + bs8;
            vt[(rb + 1) * VT_STRIDE + ccol + 8] = D[nb * 4 + 3] + bs8;
        }
        __syncthreads();

        // ---- per-row c = 2*(v_new.z)/||v_new||^2  (8 rows per warp) ----
        const float* zt = z + ((size_t)tile << 14);
        #pragma unroll 4
        for (int j = 0; j < 8; j++) {
            const int r = wid * 8 + j;
            const float* zr = zt + r * 128;
            float dot = 0.f, ns = 0.f;
            #pragma unroll
            for (int q = 0; q < 4; q++) {
                const int c = lane + q * 32;
                const float vn = vt[r * VT_STRIDE + c];
                const float zz = __ldg(zr + c);
                dot = fmaf(vn, zz, dot);
                ns  = fmaf(vn, vn, ns);
            }
            #pragma unroll
            for (int o = 16; o > 0; o >>= 1) {
                dot += __shfl_xor_sync(0xFFFFFFFFu, dot, o);
                ns  += __shfl_xor_sync(0xFFFFFFFFu, ns,  o);
            }
            if (lane == 0) cvals[r] = 2.0f * dot / ns;
        }
        __syncthreads();

        // ---- out = z - c[r]*v_new  (32 elems per thread) ----
        float* ot = out + ((size_t)tile << 14);
        #pragma unroll 8
        for (int i = 0; i < 32; i++) {
            const int e = tid + i * NTHREADS;
            const int r = e >> 7;
            const int c = e & 127;
            ot[e] = fmaf(-cvals[r], vt[r * VT_STRIDE + c], __ldg(zt + e));
        }
        __syncthreads();
    }
}

extern "C" void kernel_launch(void* const* d_in, const int* in_sizes, int n_in,
                              void* d_out, int out_size) {
    const float* z = (const float*)d_in[0];
    const float* v = (const float*)d_in[1];
    const float* W = (const float*)d_in[2];
    const float* b = (const float*)d_in[3];
    float* out = (float*)d_out;

    const int ntiles = in_sizes[0] >> 14;   // rows/128

    cudaFuncSetAttribute(hh_kernel, cudaFuncAttributeMaxDynamicSharedMemorySize, SM_TOTAL);

    int sms = 148;
    cudaDeviceGetAttribute(&sms, cudaDevAttrMultiProcessorCount, 0);
    int grid = sms;
    if (grid > ntiles) grid = ntiles;
    if (grid < 1) grid = 1;

    hh_kernel<<<grid, NTHREADS, SM_TOTAL>>>(z, v, W, b, out, ntiles);
}